// round 9
// baseline (speedup 1.0000x reference)
#include <cuda_runtime.h>
#include <stdint.h>
#include <math.h>

#define NTOK 4096
#define DIM 1024
#define NHEADS 16
#define HD 64
#define QKV_N 3072
#define SCALE 0.125f   // 1/sqrt(64)

// ---------------- scratch (no allocations allowed) ----------------
__device__ float g_qkv[NTOK * QKV_N];
__device__ float g_Q[NHEADS * NTOK * HD];
__device__ float g_K[NHEADS * NTOK * HD];
__device__ float g_V[NHEADS * NTOK * HD];
__device__ float g_attn[NTOK * DIM];

__device__ __forceinline__ uint32_t cvt_tf32(float x) {
    uint32_t r;
    asm("cvt.rna.tf32.f32 %0, %1;" : "=r"(r) : "f"(x));
    return r;
}

__device__ __forceinline__ void mma_tf32(float& c0, float& c1, float& c2, float& c3,
                                         uint32_t a0, uint32_t a1, uint32_t a2, uint32_t a3,
                                         uint32_t b0, uint32_t b1) {
    asm volatile(
        "mma.sync.aligned.m16n8k8.row.col.f32.tf32.tf32.f32 "
        "{%0,%1,%2,%3}, {%4,%5,%6,%7}, {%8,%9}, {%0,%1,%2,%3};"
        : "+f"(c0), "+f"(c1), "+f"(c2), "+f"(c3)
        : "r"(a0), "r"(a1), "r"(a2), "r"(a3), "r"(b0), "r"(b1));
}

// ---------------- tf32 MMA GEMM with register-prefetch pipeline ----------------
#define GBM 128
#define GBN 128
#define GBK 16
#define GST 136

__global__ __launch_bounds__(256, 2) void gemm_tf32_kernel(
    const float* __restrict__ A, const float* __restrict__ B,
    const float* __restrict__ bias, float* __restrict__ C,
    int M, int N, int K)
{
    __shared__ float Ast[GBK][GST];
    __shared__ float Bs[GBK][GST];

    const int tid = threadIdx.x;
    const int wid = tid >> 5;
    const int lane = tid & 31;
    const int qr = lane >> 2;
    const int qc = lane & 3;
    const int wm = wid >> 2;
    const int wn = wid & 3;
    const int rowBase = blockIdx.y * GBM;
    const int colBase = blockIdx.x * GBN;

    int ar[2], ac[2], br[2], bc[2];
    #pragma unroll
    for (int i = 0; i < 2; i++) {
        int v = tid + i * 256;
        ar[i] = v >> 2;  ac[i] = (v & 3) * 4;
        br[i] = v >> 5;  bc[i] = (v & 31) * 4;
    }

    float acc[4][4][4];
    #pragma unroll
    for (int mi = 0; mi < 4; mi++)
        #pragma unroll
        for (int ni = 0; ni < 4; ni++)
            #pragma unroll
            for (int r = 0; r < 4; r++) acc[mi][ni][r] = 0.f;

    float4 pa[2], pb[2];
    #pragma unroll
    for (int i = 0; i < 2; i++) {
        pa[i] = *(const float4*)&A[(size_t)(rowBase + ar[i]) * K + ac[i]];
        pb[i] = *(const float4*)&B[(size_t)br[i] * N + colBase + bc[i]];
    }

    for (int k0 = 0; k0 < K; k0 += GBK) {
        #pragma unroll
        for (int i = 0; i < 2; i++) {
            Ast[ac[i] + 0][ar[i]] = __uint_as_float(cvt_tf32(pa[i].x));
            Ast[ac[i] + 1][ar[i]] = __uint_as_float(cvt_tf32(pa[i].y));
            Ast[ac[i] + 2][ar[i]] = __uint_as_float(cvt_tf32(pa[i].z));
            Ast[ac[i] + 3][ar[i]] = __uint_as_float(cvt_tf32(pa[i].w));
            float4 g;
            g.x = __uint_as_float(cvt_tf32(pb[i].x));
            g.y = __uint_as_float(cvt_tf32(pb[i].y));
            g.z = __uint_as_float(cvt_tf32(pb[i].z));
            g.w = __uint_as_float(cvt_tf32(pb[i].w));
            *(float4*)&Bs[br[i]][bc[i]] = g;
        }
        __syncthreads();

        if (k0 + GBK < K) {
            #pragma unroll
            for (int i = 0; i < 2; i++) {
                pa[i] = *(const float4*)&A[(size_t)(rowBase + ar[i]) * K + (k0 + GBK) + ac[i]];
                pb[i] = *(const float4*)&B[(size_t)(k0 + GBK + br[i]) * N + colBase + bc[i]];
            }
        }

        #pragma unroll
        for (int kk = 0; kk < 2; kk++) {
            uint32_t af[4][4], bf[4][2];
            #pragma unroll
            for (int mi = 0; mi < 4; mi++) {
                int m = wm * 64 + mi * 16;
                af[mi][0] = __float_as_uint(Ast[kk * 8 + qc]    [m + qr]);
                af[mi][1] = __float_as_uint(Ast[kk * 8 + qc]    [m + qr + 8]);
                af[mi][2] = __float_as_uint(Ast[kk * 8 + qc + 4][m + qr]);
                af[mi][3] = __float_as_uint(Ast[kk * 8 + qc + 4][m + qr + 8]);
            }
            #pragma unroll
            for (int ni = 0; ni < 4; ni++) {
                int n = wn * 32 + ni * 8;
                bf[ni][0] = __float_as_uint(Bs[kk * 8 + qc]    [n + qr]);
                bf[ni][1] = __float_as_uint(Bs[kk * 8 + qc + 4][n + qr]);
            }
            #pragma unroll
            for (int mi = 0; mi < 4; mi++)
                #pragma unroll
                for (int ni = 0; ni < 4; ni++)
                    mma_tf32(acc[mi][ni][0], acc[mi][ni][1], acc[mi][ni][2], acc[mi][ni][3],
                             af[mi][0], af[mi][1], af[mi][2], af[mi][3],
                             bf[ni][0], bf[ni][1]);
        }
        __syncthreads();
    }

    #pragma unroll
    for (int mi = 0; mi < 4; mi++) {
        int m = rowBase + wm * 64 + mi * 16;
        #pragma unroll
        for (int ni = 0; ni < 4; ni++) {
            int n = colBase + wn * 32 + ni * 8 + 2 * qc;
            float bx = bias[n], by = bias[n + 1];
            float2 w0, w1;
            w0.x = acc[mi][ni][0] + bx;  w0.y = acc[mi][ni][1] + by;
            w1.x = acc[mi][ni][2] + bx;  w1.y = acc[mi][ni][3] + by;
            *(float2*)&C[(size_t)(m + qr) * N + n] = w0;
            *(float2*)&C[(size_t)(m + qr + 8) * N + n] = w1;
        }
    }
}

// ---------------- RoPE + split ----------------
__global__ void rope_split_kernel(const float* __restrict__ cosb,
                                  const float* __restrict__ sinb)
{
    int idx = blockIdx.x * blockDim.x + threadIdx.x;
    if (idx >= NTOK * NHEADS * 32) return;
    int d = idx & 31;
    int h = (idx >> 5) & 15;
    int n = idx >> 9;

    const float* base = g_qkv + (size_t)n * QKV_N;
    float c = cosb[n * 32 + d];
    float s = sinb[n * 32 + d];

    size_t ho = ((size_t)h * NTOK + n) * HD;

    float x1 = base[h * HD + d];
    float x2 = base[h * HD + d + 32];
    g_Q[ho + d]      = x1 * c - x2 * s;
    g_Q[ho + d + 32] = x2 * c + x1 * s;

    float y1 = base[DIM + h * HD + d];
    float y2 = base[DIM + h * HD + d + 32];
    g_K[ho + d]      = y1 * c - y2 * s;
    g_K[ho + d + 32] = y2 * c + y1 * s;

    g_V[ho + d]      = base[2 * DIM + h * HD + d];
    g_V[ho + d + 32] = base[2 * DIM + h * HD + d + 32];
}

// ---------------- flash attention, grouped smem layout ----------------
// Grouped layout: element (row, col) at row*KROW + (col%4)*20 + col/4.
// A thread's 16 B-frag words (all 8 k-steps of one n8 block) are contiguous.
#define ATT_BQ 128
#define ATT_BK 64
#define KROW 80

__global__ __launch_bounds__(256) void attn_mma_kernel()
{
    extern __shared__ float sm[];
    float* Ksm = sm;                          // [64][80] K grouped (tf32 bits)
    float* VTs = sm + ATT_BK * KROW;          // [64][80] V^T grouped (row=hd, col=kpos)
    float* Psm = sm + 2 * ATT_BK * KROW;      // [128][80] P grouped

    const int tid = threadIdx.x;
    const int h = blockIdx.y;
    const int q0 = blockIdx.x * ATT_BQ;
    const int wid = tid >> 5;
    const int lane = tid & 31;
    const int qr = lane >> 2;
    const int qc = lane & 3;

    const float* qbase = g_Q + ((size_t)h * NTOK + q0 + wid * 16) * HD;
    uint32_t qf[8][4];
    #pragma unroll
    for (int kk = 0; kk < 8; kk++) {
        qf[kk][0] = cvt_tf32(qbase[(size_t)(qr)     * HD + kk * 8 + qc]     * SCALE);
        qf[kk][1] = cvt_tf32(qbase[(size_t)(qr + 8) * HD + kk * 8 + qc]     * SCALE);
        qf[kk][2] = cvt_tf32(qbase[(size_t)(qr)     * HD + kk * 8 + qc + 4] * SCALE);
        qf[kk][3] = cvt_tf32(qbase[(size_t)(qr + 8) * HD + kk * 8 + qc + 4] * SCALE);
    }

    float m0 = -1e30f, m1 = -1e30f, l0 = 0.f, l1 = 0.f;
    float o[8][4];
    #pragma unroll
    for (int nb = 0; nb < 8; nb++)
        #pragma unroll
        for (int r = 0; r < 4; r++) o[nb][r] = 0.f;

    const float* kb = g_K + (size_t)h * NTOK * HD;
    const float* vb = g_V + (size_t)h * NTOK * HD;

    // per-warp fragment base offsets in grouped layout
    const int kfragBase = qr * KROW + qc * 20;            // + nb*8*KROW
    const int pRow0 = (wid * 16 + qr) * KROW + qc * 20;
    const int pRow1 = pRow0 + 8 * KROW;

    #pragma unroll 1
    for (int t = 0; t < NTOK; t += ATT_BK) {
        // ---- tile load: K grouped, V transposed+grouped ----
        #pragma unroll
        for (int i = 0; i < 4; i++) {
            int v = tid + i * 256;
            int r = v >> 4;            // kpos 0..63
            int c = (v & 15) * 4;      // hd 0,4,...,60
            float4 fk = *(const float4*)&kb[(size_t)(t + r) * HD + c];
            // K: (row=kpos r, col=hd c+j) -> r*KROW + j*20 + c/4
            int kbase = r * KROW + (c >> 2);
            Ksm[kbase +  0] = __uint_as_float(cvt_tf32(fk.x));
            Ksm[kbase + 20] = __uint_as_float(cvt_tf32(fk.y));
            Ksm[kbase + 40] = __uint_as_float(cvt_tf32(fk.z));
            Ksm[kbase + 60] = __uint_as_float(cvt_tf32(fk.w));
            float4 fv = *(const float4*)&vb[(size_t)(t + r) * HD + c];
            // V^T: (row=hd c+j, col=kpos r) -> (c+j)*KROW + (r%4)*20 + r/4
            int vbase = c * KROW + (r & 3) * 20 + (r >> 2);
            VTs[vbase + 0 * KROW] = __uint_as_float(cvt_tf32(fv.x));
            VTs[vbase + 1 * KROW] = __uint_as_float(cvt_tf32(fv.y));
            VTs[vbase + 2 * KROW] = __uint_as_float(cvt_tf32(fv.z));
            VTs[vbase + 3 * KROW] = __uint_as_float(cvt_tf32(fv.w));
        }
        __syncthreads();

        // ---- S = Q K^T : nb pairs, 4 LDS.128 per nb ----
        float sfr[8][4];
        #pragma unroll
        for (int nb = 0; nb < 8; nb++)
            #pragma unroll
            for (int r = 0; r < 4; r++) sfr[nb][r] = 0.f;

        #pragma unroll
        for (int nb = 0; nb < 8; nb += 2) {
            const float* ka = &Ksm[kfragBase + (nb * 8) * KROW];
            const float* kbp = &Ksm[kfragBase + ((nb + 1) * 8) * KROW];
            float4 a0 = *(const float4*)&ka[0],  a1 = *(const float4*)&ka[4];
            float4 a2 = *(const float4*)&ka[8],  a3 = *(const float4*)&ka[12];
            float4 b0 = *(const float4*)&kbp[0], b1 = *(const float4*)&kbp[4];
            float4 b2 = *(const float4*)&kbp[8], b3 = *(const float4*)&kbp[12];
            const float ra[16] = {a0.x,a0.y,a0.z,a0.w, a1.x,a1.y,a1.z,a1.w,
                                  a2.x,a2.y,a2.z,a2.w, a3.x,a3.y,a3.z,a3.w};
            const float rb[16] = {b0.x,b0.y,b0.z,b0.w, b1.x,b1.y,b1.z,b1.w,
                                  b2.x,b2.y,b2.z,b2.w, b3.x,b3.y,b3.z,b3.w};
            #pragma unroll
            for (int kk = 0; kk < 8; kk++) {
                mma_tf32(sfr[nb][0], sfr[nb][1], sfr[nb][2], sfr[nb][3],
                         qf[kk][0], qf[kk][1], qf[kk][2], qf[kk][3],
                         __float_as_uint(ra[2 * kk]), __float_as_uint(ra[2 * kk + 1]));
                mma_tf32(sfr[nb+1][0], sfr[nb+1][1], sfr[nb+1][2], sfr[nb+1][3],
                         qf[kk][0], qf[kk][1], qf[kk][2], qf[kk][3],
                         __float_as_uint(rb[2 * kk]), __float_as_uint(rb[2 * kk + 1]));
            }
        }

        // ---- online softmax ----
        float mt0 = m0, mt1 = m1;
        #pragma unroll
        for (int nb = 0; nb < 8; nb++) {
            mt0 = fmaxf(mt0, fmaxf(sfr[nb][0], sfr[nb][1]));
            mt1 = fmaxf(mt1, fmaxf(sfr[nb][2], sfr[nb][3]));
        }
        mt0 = fmaxf(mt0, __shfl_xor_sync(0xffffffff, mt0, 1));
        mt0 = fmaxf(mt0, __shfl_xor_sync(0xffffffff, mt0, 2));
        mt1 = fmaxf(mt1, __shfl_xor_sync(0xffffffff, mt1, 1));
        mt1 = fmaxf(mt1, __shfl_xor_sync(0xffffffff, mt1, 2));

        float c0 = __expf(m0 - mt0);
        float c1 = __expf(m1 - mt1);
        m0 = mt0; m1 = mt1;
        l0 *= c0; l1 *= c1;
        #pragma unroll
        for (int nb = 0; nb < 8; nb++) {
            o[nb][0] *= c0; o[nb][1] *= c0;
            o[nb][2] *= c1; o[nb][3] *= c1;
        }

        // ---- P = exp(S-m) -> grouped Psm ----
        {
            int g = (2 * qc) & 3;               // 0 or 2
            int r0 = (wid * 16 + qr) * KROW;
            int r1 = r0 + 8 * KROW;
            #pragma unroll
            for (int nb = 0; nb < 8; nb++) {
                float p0 = __expf(sfr[nb][0] - m0);
                float p1 = __expf(sfr[nb][1] - m0);
                float p2 = __expf(sfr[nb][2] - m1);
                float p3 = __expf(sfr[nb][3] - m1);
                l0 += p0 + p1;
                l1 += p2 + p3;
                int idx = 2 * nb + ((2 * qc) >> 2);   // col/4
                Psm[r0 + g * 20 + idx]        = __uint_as_float(cvt_tf32(p0));
                Psm[r0 + (g + 1) * 20 + idx]  = __uint_as_float(cvt_tf32(p1));
                Psm[r1 + g * 20 + idx]        = __uint_as_float(cvt_tf32(p2));
                Psm[r1 + (g + 1) * 20 + idx]  = __uint_as_float(cvt_tf32(p3));
            }
        }
        __syncwarp();

        // ---- O += P V : P A-frags once (8 LDS.128), V^T 4 LDS.128 per nb ----
        {
            float4 pl0 = *(const float4*)&Psm[pRow0 + 0];
            float4 pl1 = *(const float4*)&Psm[pRow0 + 4];
            float4 pl2 = *(const float4*)&Psm[pRow0 + 8];
            float4 pl3 = *(const float4*)&Psm[pRow0 + 12];
            float4 ph0 = *(const float4*)&Psm[pRow1 + 0];
            float4 ph1 = *(const float4*)&Psm[pRow1 + 4];
            float4 ph2 = *(const float4*)&Psm[pRow1 + 8];
            float4 ph3 = *(const float4*)&Psm[pRow1 + 12];
            const float plo[16] = {pl0.x,pl0.y,pl0.z,pl0.w, pl1.x,pl1.y,pl1.z,pl1.w,
                                   pl2.x,pl2.y,pl2.z,pl2.w, pl3.x,pl3.y,pl3.z,pl3.w};
            const float phi[16] = {ph0.x,ph0.y,ph0.z,ph0.w, ph1.x,ph1.y,ph1.z,ph1.w,
                                   ph2.x,ph2.y,ph2.z,ph2.w, ph3.x,ph3.y,ph3.z,ph3.w};

            #pragma unroll
            for (int nb = 0; nb < 8; nb += 2) {
                const float* va = &VTs[kfragBase + (nb * 8) * KROW];
                const float* vbp = &VTs[kfragBase + ((nb + 1) * 8) * KROW];
                float4 a0 = *(const float4*)&va[0],  a1 = *(const float4*)&va[4];
                float4 a2 = *(const float4*)&va[8],  a3 = *(const float4*)&va[12];
                float4 b0 = *(const float4*)&vbp[0], b1 = *(const float4*)&vbp[4];
                float4 b2 = *(const float4*)&vbp[8], b3 = *(const float4*)&vbp[12];
                const float ra[16] = {a0.x,a0.y,a0.z,a0.w, a1.x,a1.y,a1.z,a1.w,
                                      a2.x,a2.y,a2.z,a2.w, a3.x,a3.y,a3.z,a3.w};
                const float rb[16] = {b0.x,b0.y,b0.z,b0.w, b1.x,b1.y,b1.z,b1.w,
                                      b2.x,b2.y,b2.z,b2.w, b3.x,b3.y,b3.z,b3.w};
                #pragma unroll
                for (int kk = 0; kk < 8; kk++) {
                    mma_tf32(o[nb][0], o[nb][1], o[nb][2], o[nb][3],
                             __float_as_uint(plo[2 * kk]), __float_as_uint(phi[2 * kk]),
                             __float_as_uint(plo[2 * kk + 1]), __float_as_uint(phi[2 * kk + 1]),
                             __float_as_uint(ra[2 * kk]), __float_as_uint(ra[2 * kk + 1]));
                    mma_tf32(o[nb+1][0], o[nb+1][1], o[nb+1][2], o[nb+1][3],
                             __float_as_uint(plo[2 * kk]), __float_as_uint(phi[2 * kk]),
                             __float_as_uint(plo[2 * kk + 1]), __float_as_uint(phi[2 * kk + 1]),
                             __float_as_uint(rb[2 * kk]), __float_as_uint(rb[2 * kk + 1]));
                }
            }
        }
        __syncthreads();
    }

    l0 += __shfl_xor_sync(0xffffffff, l0, 1);
    l0 += __shfl_xor_sync(0xffffffff, l0, 2);
    l1 += __shfl_xor_sync(0xffffffff, l1, 1);
    l1 += __shfl_xor_sync(0xffffffff, l1, 2);
    float inv0 = 1.f / l0;
    float inv1 = 1.f / l1;

    int row0 = q0 + wid * 16 + qr;
    #pragma unroll
    for (int nb = 0; nb < 8; nb++) {
        int col = h * HD + nb * 8 + 2 * qc;
        float2 w0, w1;
        w0.x = o[nb][0] * inv0; w0.y = o[nb][1] * inv0;
        w1.x = o[nb][2] * inv1; w1.y = o[nb][3] * inv1;
        *(float2*)&g_attn[(size_t)row0 * DIM + col] = w0;
        *(float2*)&g_attn[(size_t)(row0 + 8) * DIM + col] = w1;
    }
}

#define ATT_SMEM ((2 * ATT_BK * KROW + ATT_BQ * KROW) * 4)

// ---------------- launch ----------------
extern "C" void kernel_launch(void* const* d_in, const int* in_sizes, int n_in,
                              void* d_out, int out_size)
{
    const float* x      = (const float*)d_in[0];
    const float* cosb   = (const float*)d_in[1];
    const float* sinb   = (const float*)d_in[2];
    const float* w_qkv  = (const float*)d_in[3];
    const float* b_qkv  = (const float*)d_in[4];
    const float* w_proj = (const float*)d_in[5];
    const float* b_proj = (const float*)d_in[6];
    float* out = (float*)d_out;

    float *p_qkv, *p_attn;
    cudaGetSymbolAddress((void**)&p_qkv, g_qkv);
    cudaGetSymbolAddress((void**)&p_attn, g_attn);

    cudaFuncSetAttribute(attn_mma_kernel,
                         cudaFuncAttributeMaxDynamicSharedMemorySize, ATT_SMEM);

    // 1) QKV GEMM
    {
        dim3 grid(QKV_N / GBN, NTOK / GBM);
        gemm_tf32_kernel<<<grid, 256>>>(x, w_qkv, b_qkv, p_qkv, NTOK, QKV_N, DIM);
    }
    // 2) RoPE + split
    {
        int total = NTOK * NHEADS * 32;
        rope_split_kernel<<<(total + 255) / 256, 256>>>(cosb, sinb);
    }
    // 3) attention
    {
        dim3 grid(NTOK / ATT_BQ, NHEADS);
        attn_mma_kernel<<<grid, 256, ATT_SMEM>>>();
    }
    // 4) proj GEMM
    {
        dim3 grid(DIM / GBN, NTOK / GBM);
        gemm_tf32_kernel<<<grid, 256>>>(p_attn, w_proj, b_proj, out, NTOK, DIM, DIM);
    }
}

// round 14
// speedup vs baseline: 1.1900x; 1.1900x over previous
#include <cuda_runtime.h>
#include <stdint.h>
#include <math.h>

#define NTOK 4096
#define DIM 1024
#define NHEADS 16
#define HD 64
#define QKV_N 3072
#define SCALE 0.125f   // 1/sqrt(64)

// ---------------- scratch (no allocations allowed) ----------------
__device__ float g_qkv[NTOK * QKV_N];
__device__ float g_Q[NHEADS * NTOK * HD];
__device__ float g_K[NHEADS * NTOK * HD];
__device__ float g_V[NHEADS * NTOK * HD];
__device__ float g_attn[NTOK * DIM];

__device__ __forceinline__ uint32_t cvt_tf32(float x) {
    uint32_t r;
    asm("cvt.rna.tf32.f32 %0, %1;" : "=r"(r) : "f"(x));
    return r;
}

__device__ __forceinline__ void mma_tf32(float& c0, float& c1, float& c2, float& c3,
                                         uint32_t a0, uint32_t a1, uint32_t a2, uint32_t a3,
                                         uint32_t b0, uint32_t b1) {
    asm volatile(
        "mma.sync.aligned.m16n8k8.row.col.f32.tf32.tf32.f32 "
        "{%0,%1,%2,%3}, {%4,%5,%6,%7}, {%8,%9}, {%0,%1,%2,%3};"
        : "+f"(c0), "+f"(c1), "+f"(c2), "+f"(c3)
        : "r"(a0), "r"(a1), "r"(a2), "r"(a3), "r"(b0), "r"(b1));
}

// ldmatrix x4: four 8x8 b16 matrices = two 8x8 b32 matrices.
__device__ __forceinline__ void ldsm_x4(uint32_t& r0, uint32_t& r1,
                                        uint32_t& r2, uint32_t& r3, uint32_t saddr) {
    asm volatile("ldmatrix.sync.aligned.m8n8.x4.shared.b16 {%0,%1,%2,%3}, [%4];"
                 : "=r"(r0), "=r"(r1), "=r"(r2), "=r"(r3) : "r"(saddr));
}

// ---------------- tf32 MMA GEMM with register-prefetch pipeline ----------------
#define GBM 128
#define GBN 128
#define GBK 16
#define GST 136

__global__ __launch_bounds__(256, 2) void gemm_tf32_kernel(
    const float* __restrict__ A, const float* __restrict__ B,
    const float* __restrict__ bias, float* __restrict__ C,
    int M, int N, int K)
{
    __shared__ float Ast[GBK][GST];
    __shared__ float Bs[GBK][GST];

    const int tid = threadIdx.x;
    const int wid = tid >> 5;
    const int lane = tid & 31;
    const int qr = lane >> 2;
    const int qc = lane & 3;
    const int wm = wid >> 2;
    const int wn = wid & 3;
    const int rowBase = blockIdx.y * GBM;
    const int colBase = blockIdx.x * GBN;

    int ar[2], ac[2], br[2], bc[2];
    #pragma unroll
    for (int i = 0; i < 2; i++) {
        int v = tid + i * 256;
        ar[i] = v >> 2;  ac[i] = (v & 3) * 4;
        br[i] = v >> 5;  bc[i] = (v & 31) * 4;
    }

    float acc[4][4][4];
    #pragma unroll
    for (int mi = 0; mi < 4; mi++)
        #pragma unroll
        for (int ni = 0; ni < 4; ni++)
            #pragma unroll
            for (int r = 0; r < 4; r++) acc[mi][ni][r] = 0.f;

    float4 pa[2], pb[2];
    #pragma unroll
    for (int i = 0; i < 2; i++) {
        pa[i] = *(const float4*)&A[(size_t)(rowBase + ar[i]) * K + ac[i]];
        pb[i] = *(const float4*)&B[(size_t)br[i] * N + colBase + bc[i]];
    }

    for (int k0 = 0; k0 < K; k0 += GBK) {
        #pragma unroll
        for (int i = 0; i < 2; i++) {
            Ast[ac[i] + 0][ar[i]] = __uint_as_float(cvt_tf32(pa[i].x));
            Ast[ac[i] + 1][ar[i]] = __uint_as_float(cvt_tf32(pa[i].y));
            Ast[ac[i] + 2][ar[i]] = __uint_as_float(cvt_tf32(pa[i].z));
            Ast[ac[i] + 3][ar[i]] = __uint_as_float(cvt_tf32(pa[i].w));
            float4 g;
            g.x = __uint_as_float(cvt_tf32(pb[i].x));
            g.y = __uint_as_float(cvt_tf32(pb[i].y));
            g.z = __uint_as_float(cvt_tf32(pb[i].z));
            g.w = __uint_as_float(cvt_tf32(pb[i].w));
            *(float4*)&Bs[br[i]][bc[i]] = g;
        }
        __syncthreads();

        if (k0 + GBK < K) {
            #pragma unroll
            for (int i = 0; i < 2; i++) {
                pa[i] = *(const float4*)&A[(size_t)(rowBase + ar[i]) * K + (k0 + GBK) + ac[i]];
                pb[i] = *(const float4*)&B[(size_t)(k0 + GBK + br[i]) * N + colBase + bc[i]];
            }
        }

        #pragma unroll
        for (int kk = 0; kk < 2; kk++) {
            uint32_t af[4][4], bf[4][2];
            #pragma unroll
            for (int mi = 0; mi < 4; mi++) {
                int m = wm * 64 + mi * 16;
                af[mi][0] = __float_as_uint(Ast[kk * 8 + qc]    [m + qr]);
                af[mi][1] = __float_as_uint(Ast[kk * 8 + qc]    [m + qr + 8]);
                af[mi][2] = __float_as_uint(Ast[kk * 8 + qc + 4][m + qr]);
                af[mi][3] = __float_as_uint(Ast[kk * 8 + qc + 4][m + qr + 8]);
            }
            #pragma unroll
            for (int ni = 0; ni < 4; ni++) {
                int n = wn * 32 + ni * 8;
                bf[ni][0] = __float_as_uint(Bs[kk * 8 + qc]    [n + qr]);
                bf[ni][1] = __float_as_uint(Bs[kk * 8 + qc + 4][n + qr]);
            }
            #pragma unroll
            for (int mi = 0; mi < 4; mi++)
                #pragma unroll
                for (int ni = 0; ni < 4; ni++)
                    mma_tf32(acc[mi][ni][0], acc[mi][ni][1], acc[mi][ni][2], acc[mi][ni][3],
                             af[mi][0], af[mi][1], af[mi][2], af[mi][3],
                             bf[ni][0], bf[ni][1]);
        }
        __syncthreads();
    }

    #pragma unroll
    for (int mi = 0; mi < 4; mi++) {
        int m = rowBase + wm * 64 + mi * 16;
        #pragma unroll
        for (int ni = 0; ni < 4; ni++) {
            int n = colBase + wn * 32 + ni * 8 + 2 * qc;
            float bx = bias[n], by = bias[n + 1];
            float2 w0, w1;
            w0.x = acc[mi][ni][0] + bx;  w0.y = acc[mi][ni][1] + by;
            w1.x = acc[mi][ni][2] + bx;  w1.y = acc[mi][ni][3] + by;
            *(float2*)&C[(size_t)(m + qr) * N + n] = w0;
            *(float2*)&C[(size_t)(m + qr + 8) * N + n] = w1;
        }
    }
}

// ---------------- RoPE + split ----------------
__global__ void rope_split_kernel(const float* __restrict__ cosb,
                                  const float* __restrict__ sinb)
{
    int idx = blockIdx.x * blockDim.x + threadIdx.x;
    if (idx >= NTOK * NHEADS * 32) return;
    int d = idx & 31;
    int h = (idx >> 5) & 15;
    int n = idx >> 9;

    const float* base = g_qkv + (size_t)n * QKV_N;
    float c = cosb[n * 32 + d];
    float s = sinb[n * 32 + d];

    size_t ho = ((size_t)h * NTOK + n) * HD;

    float x1 = base[h * HD + d];
    float x2 = base[h * HD + d + 32];
    g_Q[ho + d]      = x1 * c - x2 * s;
    g_Q[ho + d + 32] = x2 * c + x1 * s;

    float y1 = base[DIM + h * HD + d];
    float y2 = base[DIM + h * HD + d + 32];
    g_K[ho + d]      = y1 * c - y2 * s;
    g_K[ho + d + 32] = y2 * c + y1 * s;

    g_V[ho + d]      = base[2 * DIM + h * HD + d];
    g_V[ho + d + 32] = base[2 * DIM + h * HD + d + 32];
}

// ---------------- flash attention: tf32 mma + ldmatrix fragments ----------------
// K/V/P all natural row-major (stride KST). B-frags for S and A-frags for PV
// come from ldmatrix.x4 (b16 view of 8x8 b32 tiles). V B-frags stay scalar.
#define ATT_BQ 128
#define ATT_BK 64
#define KST 68

__global__ __launch_bounds__(256) void attn_mma_kernel()
{
    extern __shared__ float sm[];
    float (*Ks)[KST] = (float(*)[KST])sm;                       // [64][68]
    float (*Vs)[KST] = (float(*)[KST])(sm + ATT_BK * KST);      // [64][68]
    float (*Ps)[KST] = (float(*)[KST])(sm + 2 * ATT_BK * KST);  // [128][68]

    const int tid = threadIdx.x;
    const int h = blockIdx.y;
    const int q0 = blockIdx.x * ATT_BQ;
    const int wid = tid >> 5;
    const int lane = tid & 31;
    const int qr = lane >> 2;
    const int qc = lane & 3;

    // per-lane ldmatrix row addresses (bytes)
    const uint32_t ks_base = (uint32_t)__cvta_generic_to_shared(&Ks[0][0]);
    const uint32_t ps_base = (uint32_t)__cvta_generic_to_shared(&Ps[0][0]);
    // K B-frags: lane -> row (l&7), col-offset (l>>3)*4 within a kk-pair block
    const uint32_t ks_lane = ks_base + (((lane & 7) * KST + (lane >> 3) * 4) << 2);
    // P A-frags: lanes 0-7: (r, c0), 8-15: (r, c0+4), 16-23: (r+8, c0), 24-31: (r+8, c0+4)
    const uint32_t ps_lane = ps_base +
        ((((wid * 16 + (lane & 7) + ((lane >> 4) & 1) * 8) * KST) + ((lane >> 3) & 1) * 4) << 2);

    const float* qbase = g_Q + ((size_t)h * NTOK + q0 + wid * 16) * HD;
    uint32_t qf[8][4];
    #pragma unroll
    for (int kk = 0; kk < 8; kk++) {
        qf[kk][0] = cvt_tf32(qbase[(size_t)(qr)     * HD + kk * 8 + qc]     * SCALE);
        qf[kk][1] = cvt_tf32(qbase[(size_t)(qr + 8) * HD + kk * 8 + qc]     * SCALE);
        qf[kk][2] = cvt_tf32(qbase[(size_t)(qr)     * HD + kk * 8 + qc + 4] * SCALE);
        qf[kk][3] = cvt_tf32(qbase[(size_t)(qr + 8) * HD + kk * 8 + qc + 4] * SCALE);
    }

    float m0 = -1e30f, m1 = -1e30f, l0 = 0.f, l1 = 0.f;
    float o[8][4];
    #pragma unroll
    for (int nb = 0; nb < 8; nb++)
        #pragma unroll
        for (int r = 0; r < 4; r++) o[nb][r] = 0.f;

    const float* kb = g_K + (size_t)h * NTOK * HD;
    const float* vb = g_V + (size_t)h * NTOK * HD;

    #pragma unroll 1
    for (int t = 0; t < NTOK; t += ATT_BK) {
        // ---- K/V tile load (coalesced, tf32-converted) ----
        #pragma unroll
        for (int i = 0; i < 4; i++) {
            int v = tid + i * 256;
            int r = v >> 4;
            int c = (v & 15) * 4;
            float4 fk = *(const float4*)&kb[(size_t)(t + r) * HD + c];
            float4 fv = *(const float4*)&vb[(size_t)(t + r) * HD + c];
            float4 gk, gv;
            gk.x = __uint_as_float(cvt_tf32(fk.x)); gk.y = __uint_as_float(cvt_tf32(fk.y));
            gk.z = __uint_as_float(cvt_tf32(fk.z)); gk.w = __uint_as_float(cvt_tf32(fk.w));
            gv.x = __uint_as_float(cvt_tf32(fv.x)); gv.y = __uint_as_float(cvt_tf32(fv.y));
            gv.z = __uint_as_float(cvt_tf32(fv.z)); gv.w = __uint_as_float(cvt_tf32(fv.w));
            *(float4*)&Ks[r][c] = gk;
            *(float4*)&Vs[r][c] = gv;
        }
        __syncthreads();

        // ---- S = Q K^T : B-frags via ldmatrix, nb-pair interleaved MMA chains ----
        float sfr[8][4];
        #pragma unroll
        for (int nb = 0; nb < 8; nb++)
            #pragma unroll
            for (int r = 0; r < 4; r++) sfr[nb][r] = 0.f;

        #pragma unroll
        for (int nb = 0; nb < 8; nb += 2) {
            uint32_t fA[4][4], fB[4][4];   // [kk-pair][4 words]
            #pragma unroll
            for (int kp = 0; kp < 4; kp++) {
                ldsm_x4(fA[kp][0], fA[kp][1], fA[kp][2], fA[kp][3],
                        ks_lane + (((nb * 8) * KST + kp * 16) << 2));
                ldsm_x4(fB[kp][0], fB[kp][1], fB[kp][2], fB[kp][3],
                        ks_lane + ((((nb + 1) * 8) * KST + kp * 16) << 2));
            }
            #pragma unroll
            for (int kk = 0; kk < 8; kk++) {
                int kp = kk >> 1, sel = (kk & 1) * 2;
                mma_tf32(sfr[nb][0], sfr[nb][1], sfr[nb][2], sfr[nb][3],
                         qf[kk][0], qf[kk][1], qf[kk][2], qf[kk][3],
                         fA[kp][sel], fA[kp][sel + 1]);
                mma_tf32(sfr[nb+1][0], sfr[nb+1][1], sfr[nb+1][2], sfr[nb+1][3],
                         qf[kk][0], qf[kk][1], qf[kk][2], qf[kk][3],
                         fB[kp][sel], fB[kp][sel + 1]);
            }
        }

        // ---- online softmax ----
        float mt0 = m0, mt1 = m1;
        #pragma unroll
        for (int nb = 0; nb < 8; nb++) {
            mt0 = fmaxf(mt0, fmaxf(sfr[nb][0], sfr[nb][1]));
            mt1 = fmaxf(mt1, fmaxf(sfr[nb][2], sfr[nb][3]));
        }
        mt0 = fmaxf(mt0, __shfl_xor_sync(0xffffffff, mt0, 1));
        mt0 = fmaxf(mt0, __shfl_xor_sync(0xffffffff, mt0, 2));
        mt1 = fmaxf(mt1, __shfl_xor_sync(0xffffffff, mt1, 1));
        mt1 = fmaxf(mt1, __shfl_xor_sync(0xffffffff, mt1, 2));

        float c0 = __expf(m0 - mt0);
        float c1 = __expf(m1 - mt1);
        m0 = mt0; m1 = mt1;
        l0 *= c0; l1 *= c1;
        #pragma unroll
        for (int nb = 0; nb < 8; nb++) {
            o[nb][0] *= c0; o[nb][1] *= c0;
            o[nb][2] *= c1; o[nb][3] *= c1;
        }

        // ---- P = exp(S - m) -> Ps (natural layout) ----
        #pragma unroll
        for (int nb = 0; nb < 8; nb++) {
            float p0 = __expf(sfr[nb][0] - m0);
            float p1 = __expf(sfr[nb][1] - m0);
            float p2 = __expf(sfr[nb][2] - m1);
            float p3 = __expf(sfr[nb][3] - m1);
            l0 += p0 + p1;
            l1 += p2 + p3;
            float2 w0, w1;
            w0.x = __uint_as_float(cvt_tf32(p0));
            w0.y = __uint_as_float(cvt_tf32(p1));
            w1.x = __uint_as_float(cvt_tf32(p2));
            w1.y = __uint_as_float(cvt_tf32(p3));
            *(float2*)&Ps[wid * 16 + qr]    [nb * 8 + 2 * qc] = w0;
            *(float2*)&Ps[wid * 16 + qr + 8][nb * 8 + 2 * qc] = w1;
        }
        __syncwarp();

        // ---- O += P V : A-frags via ldmatrix (reg map r0,r2,r1,r3), V scalar ----
        #pragma unroll
        for (int kk = 0; kk < 8; kk++) {
            uint32_t p0, p1, p2, p3;
            ldsm_x4(p0, p1, p2, p3, ps_lane + ((kk * 8) << 2));
            const float* vrow0 = &Vs[kk * 8 + qc][0];
            const float* vrow1 = &Vs[kk * 8 + qc + 4][0];
            #pragma unroll
            for (int nb = 0; nb < 8; nb++) {
                uint32_t b0 = __float_as_uint(vrow0[nb * 8 + qr]);
                uint32_t b1 = __float_as_uint(vrow1[nb * 8 + qr]);
                mma_tf32(o[nb][0], o[nb][1], o[nb][2], o[nb][3],
                         p0, p2, p1, p3, b0, b1);
            }
        }
        __syncthreads();
    }

    l0 += __shfl_xor_sync(0xffffffff, l0, 1);
    l0 += __shfl_xor_sync(0xffffffff, l0, 2);
    l1 += __shfl_xor_sync(0xffffffff, l1, 1);
    l1 += __shfl_xor_sync(0xffffffff, l1, 2);
    float inv0 = 1.f / l0;
    float inv1 = 1.f / l1;

    int row0 = q0 + wid * 16 + qr;
    #pragma unroll
    for (int nb = 0; nb < 8; nb++) {
        int col = h * HD + nb * 8 + 2 * qc;
        float2 w0, w1;
        w0.x = o[nb][0] * inv0; w0.y = o[nb][1] * inv0;
        w1.x = o[nb][2] * inv1; w1.y = o[nb][3] * inv1;
        *(float2*)&g_attn[(size_t)row0 * DIM + col] = w0;
        *(float2*)&g_attn[(size_t)(row0 + 8) * DIM + col] = w1;
    }
}

#define ATT_SMEM ((2 * ATT_BK * KST + ATT_BQ * KST) * 4)

// ---------------- launch ----------------
extern "C" void kernel_launch(void* const* d_in, const int* in_sizes, int n_in,
                              void* d_out, int out_size)
{
    const float* x      = (const float*)d_in[0];
    const float* cosb   = (const float*)d_in[1];
    const float* sinb   = (const float*)d_in[2];
    const float* w_qkv  = (const float*)d_in[3];
    const float* b_qkv  = (const float*)d_in[4];
    const float* w_proj = (const float*)d_in[5];
    const float* b_proj = (const float*)d_in[6];
    float* out = (float*)d_out;

    float *p_qkv, *p_attn;
    cudaGetSymbolAddress((void**)&p_qkv, g_qkv);
    cudaGetSymbolAddress((void**)&p_attn, g_attn);

    cudaFuncSetAttribute(attn_mma_kernel,
                         cudaFuncAttributeMaxDynamicSharedMemorySize, ATT_SMEM);

    // 1) QKV GEMM
    {
        dim3 grid(QKV_N / GBN, NTOK / GBM);
        gemm_tf32_kernel<<<grid, 256>>>(x, w_qkv, b_qkv, p_qkv, NTOK, QKV_N, DIM);
    }
    // 2) RoPE + split
    {
        int total = NTOK * NHEADS * 32;
        rope_split_kernel<<<(total + 255) / 256, 256>>>(cosb, sinb);
    }
    // 3) attention
    {
        dim3 grid(NTOK / ATT_BQ, NHEADS);
        attn_mma_kernel<<<grid, 256, ATT_SMEM>>>();
    }
    // 4) proj GEMM
    {
        dim3 grid(DIM / GBN, NTOK / GBM);
        gemm_tf32_kernel<<<grid, 256>>>(p_attn, w_proj, b_proj, out, NTOK, DIM, DIM);
    }
}

// round 15
// speedup vs baseline: 2.1628x; 1.8175x over previous
#include <cuda_runtime.h>
#include <cuda_fp16.h>
#include <stdint.h>
#include <math.h>

#define NTOK 4096
#define DIM 1024
#define NHEADS 16
#define HD 64
#define QKV_N 3072
#define SCALE 0.125f   // 1/sqrt(64)

// ---------------- scratch (no allocations allowed) ----------------
__device__ float g_qkv[NTOK * QKV_N];
__device__ float g_Q[NHEADS * NTOK * HD];
__device__ float g_K[NHEADS * NTOK * HD];
__device__ float g_V[NHEADS * NTOK * HD];
__device__ float g_attn[NTOK * DIM];

__device__ __forceinline__ uint32_t cvt_tf32(float x) {
    uint32_t r;
    asm("cvt.rna.tf32.f32 %0, %1;" : "=r"(r) : "f"(x));
    return r;
}

__device__ __forceinline__ uint32_t f2h2(float a, float b) {
    __half2 h = __floats2half2_rn(a, b);
    return *(uint32_t*)&h;
}

__device__ __forceinline__ void mma_tf32(float& c0, float& c1, float& c2, float& c3,
                                         uint32_t a0, uint32_t a1, uint32_t a2, uint32_t a3,
                                         uint32_t b0, uint32_t b1) {
    asm volatile(
        "mma.sync.aligned.m16n8k8.row.col.f32.tf32.tf32.f32 "
        "{%0,%1,%2,%3}, {%4,%5,%6,%7}, {%8,%9}, {%0,%1,%2,%3};"
        : "+f"(c0), "+f"(c1), "+f"(c2), "+f"(c3)
        : "r"(a0), "r"(a1), "r"(a2), "r"(a3), "r"(b0), "r"(b1));
}

__device__ __forceinline__ void mma_f16(float& c0, float& c1, float& c2, float& c3,
                                        uint32_t a0, uint32_t a1, uint32_t a2, uint32_t a3,
                                        uint32_t b0, uint32_t b1) {
    asm volatile(
        "mma.sync.aligned.m16n8k16.row.col.f32.f16.f16.f32 "
        "{%0,%1,%2,%3}, {%4,%5,%6,%7}, {%8,%9}, {%0,%1,%2,%3};"
        : "+f"(c0), "+f"(c1), "+f"(c2), "+f"(c3)
        : "r"(a0), "r"(a1), "r"(a2), "r"(a3), "r"(b0), "r"(b1));
}

__device__ __forceinline__ void ldsm_x4(uint32_t& r0, uint32_t& r1,
                                        uint32_t& r2, uint32_t& r3, uint32_t saddr) {
    asm volatile("ldmatrix.sync.aligned.m8n8.x4.shared.b16 {%0,%1,%2,%3}, [%4];"
                 : "=r"(r0), "=r"(r1), "=r"(r2), "=r"(r3) : "r"(saddr));
}

__device__ __forceinline__ void ldsm_x4t(uint32_t& r0, uint32_t& r1,
                                         uint32_t& r2, uint32_t& r3, uint32_t saddr) {
    asm volatile("ldmatrix.sync.aligned.m8n8.x4.trans.shared.b16 {%0,%1,%2,%3}, [%4];"
                 : "=r"(r0), "=r"(r1), "=r"(r2), "=r"(r3) : "r"(saddr));
}

// ---------------- tf32 MMA GEMM with register-prefetch pipeline (R8, 85us) ---
#define GBM 128
#define GBN 128
#define GBK 16
#define GST 136

__global__ __launch_bounds__(256, 2) void gemm_tf32_kernel(
    const float* __restrict__ A, const float* __restrict__ B,
    const float* __restrict__ bias, float* __restrict__ C,
    int M, int N, int K)
{
    __shared__ float Ast[GBK][GST];
    __shared__ float Bs[GBK][GST];

    const int tid = threadIdx.x;
    const int wid = tid >> 5;
    const int lane = tid & 31;
    const int qr = lane >> 2;
    const int qc = lane & 3;
    const int wm = wid >> 2;
    const int wn = wid & 3;
    const int rowBase = blockIdx.y * GBM;
    const int colBase = blockIdx.x * GBN;

    int ar[2], ac[2], br[2], bc[2];
    #pragma unroll
    for (int i = 0; i < 2; i++) {
        int v = tid + i * 256;
        ar[i] = v >> 2;  ac[i] = (v & 3) * 4;
        br[i] = v >> 5;  bc[i] = (v & 31) * 4;
    }

    float acc[4][4][4];
    #pragma unroll
    for (int mi = 0; mi < 4; mi++)
        #pragma unroll
        for (int ni = 0; ni < 4; ni++)
            #pragma unroll
            for (int r = 0; r < 4; r++) acc[mi][ni][r] = 0.f;

    float4 pa[2], pb[2];
    #pragma unroll
    for (int i = 0; i < 2; i++) {
        pa[i] = *(const float4*)&A[(size_t)(rowBase + ar[i]) * K + ac[i]];
        pb[i] = *(const float4*)&B[(size_t)br[i] * N + colBase + bc[i]];
    }

    for (int k0 = 0; k0 < K; k0 += GBK) {
        #pragma unroll
        for (int i = 0; i < 2; i++) {
            Ast[ac[i] + 0][ar[i]] = __uint_as_float(cvt_tf32(pa[i].x));
            Ast[ac[i] + 1][ar[i]] = __uint_as_float(cvt_tf32(pa[i].y));
            Ast[ac[i] + 2][ar[i]] = __uint_as_float(cvt_tf32(pa[i].z));
            Ast[ac[i] + 3][ar[i]] = __uint_as_float(cvt_tf32(pa[i].w));
            float4 g;
            g.x = __uint_as_float(cvt_tf32(pb[i].x));
            g.y = __uint_as_float(cvt_tf32(pb[i].y));
            g.z = __uint_as_float(cvt_tf32(pb[i].z));
            g.w = __uint_as_float(cvt_tf32(pb[i].w));
            *(float4*)&Bs[br[i]][bc[i]] = g;
        }
        __syncthreads();

        if (k0 + GBK < K) {
            #pragma unroll
            for (int i = 0; i < 2; i++) {
                pa[i] = *(const float4*)&A[(size_t)(rowBase + ar[i]) * K + (k0 + GBK) + ac[i]];
                pb[i] = *(const float4*)&B[(size_t)(k0 + GBK + br[i]) * N + colBase + bc[i]];
            }
        }

        #pragma unroll
        for (int kk = 0; kk < 2; kk++) {
            uint32_t af[4][4], bf[4][2];
            #pragma unroll
            for (int mi = 0; mi < 4; mi++) {
                int m = wm * 64 + mi * 16;
                af[mi][0] = __float_as_uint(Ast[kk * 8 + qc]    [m + qr]);
                af[mi][1] = __float_as_uint(Ast[kk * 8 + qc]    [m + qr + 8]);
                af[mi][2] = __float_as_uint(Ast[kk * 8 + qc + 4][m + qr]);
                af[mi][3] = __float_as_uint(Ast[kk * 8 + qc + 4][m + qr + 8]);
            }
            #pragma unroll
            for (int ni = 0; ni < 4; ni++) {
                int n = wn * 32 + ni * 8;
                bf[ni][0] = __float_as_uint(Bs[kk * 8 + qc]    [n + qr]);
                bf[ni][1] = __float_as_uint(Bs[kk * 8 + qc + 4][n + qr]);
            }
            #pragma unroll
            for (int mi = 0; mi < 4; mi++)
                #pragma unroll
                for (int ni = 0; ni < 4; ni++)
                    mma_tf32(acc[mi][ni][0], acc[mi][ni][1], acc[mi][ni][2], acc[mi][ni][3],
                             af[mi][0], af[mi][1], af[mi][2], af[mi][3],
                             bf[ni][0], bf[ni][1]);
        }
        __syncthreads();
    }

    #pragma unroll
    for (int mi = 0; mi < 4; mi++) {
        int m = rowBase + wm * 64 + mi * 16;
        #pragma unroll
        for (int ni = 0; ni < 4; ni++) {
            int n = colBase + wn * 32 + ni * 8 + 2 * qc;
            float bx = bias[n], by = bias[n + 1];
            float2 w0, w1;
            w0.x = acc[mi][ni][0] + bx;  w0.y = acc[mi][ni][1] + by;
            w1.x = acc[mi][ni][2] + bx;  w1.y = acc[mi][ni][3] + by;
            *(float2*)&C[(size_t)(m + qr) * N + n] = w0;
            *(float2*)&C[(size_t)(m + qr + 8) * N + n] = w1;
        }
    }
}

// ---------------- RoPE + split ----------------
__global__ void rope_split_kernel(const float* __restrict__ cosb,
                                  const float* __restrict__ sinb)
{
    int idx = blockIdx.x * blockDim.x + threadIdx.x;
    if (idx >= NTOK * NHEADS * 32) return;
    int d = idx & 31;
    int h = (idx >> 5) & 15;
    int n = idx >> 9;

    const float* base = g_qkv + (size_t)n * QKV_N;
    float c = cosb[n * 32 + d];
    float s = sinb[n * 32 + d];

    size_t ho = ((size_t)h * NTOK + n) * HD;

    float x1 = base[h * HD + d];
    float x2 = base[h * HD + d + 32];
    g_Q[ho + d]      = x1 * c - x2 * s;
    g_Q[ho + d + 32] = x2 * c + x1 * s;

    float y1 = base[DIM + h * HD + d];
    float y2 = base[DIM + h * HD + d + 32];
    g_K[ho + d]      = y1 * c - y2 * s;
    g_K[ho + d + 32] = y2 * c + y1 * s;

    g_V[ho + d]      = base[2 * DIM + h * HD + d];
    g_V[ho + d + 32] = base[2 * DIM + h * HD + d + 32];
}

// ---------------- flash attention: fp16 mma (m16n8k16), fp32 softmax/accum ---
// K/V/P tiles in half2-packed smem (stride 36 words = 144B, conflict-free).
// All fragments via ldmatrix: K plain .x4, V .x4.trans (natural layout), P .x4.
#define ATT_BQ 128
#define ATT_BK 64
#define H2ST 36            // half2 words per row (32 data + 4 pad)
#define H2STB 144          // bytes

__global__ __launch_bounds__(256) void attn_mma_kernel()
{
    extern __shared__ uint32_t sm2[];
    uint32_t* Ks2 = sm2;                         // [64][36] K half2
    uint32_t* Vs2 = sm2 + 64 * H2ST;             // [64][36] V half2
    uint32_t* Ps2 = sm2 + 128 * H2ST;            // [128][36] P half2

    const int tid = threadIdx.x;
    const int h = blockIdx.y;
    const int q0 = blockIdx.x * ATT_BQ;
    const int wid = tid >> 5;
    const int lane = tid & 31;
    const int qr = lane >> 2;
    const int qc = lane & 3;

    const uint32_t ks_base = (uint32_t)__cvta_generic_to_shared(Ks2);
    const uint32_t vs_base = (uint32_t)__cvta_generic_to_shared(Vs2);
    const uint32_t ps_base = (uint32_t)__cvta_generic_to_shared(Ps2);

    // K B-frags (plain): m0/m1 = b0/b1 of nb, m2/m3 of nb+1.
    // lane: row = nbsel*8 + (l&7), bytecol = bsel*16  (nbsel=(l>>4)&1, bsel=(l>>3)&1)
    const uint32_t ks_lane = ks_base + (((lane >> 4) & 1) * 8 + (lane & 7)) * H2STB
                                     + ((lane >> 3) & 1) * 16;
    // V B-frags (.trans): row = kk*16 + ksel*8 + (l&7), bytecol = nbsel*16
    const uint32_t vs_lane = vs_base + (((lane >> 3) & 1) * 8 + (lane & 7)) * H2STB
                                     + ((lane >> 4) & 1) * 16;
    // P A-frags (plain): row = wid*16 + rsel*8 + (l&7), bytecol = csel*16
    const uint32_t ps_lane = ps_base + (wid * 16 + ((lane >> 4) & 1) * 8 + (lane & 7)) * H2STB
                                     + ((lane >> 3) & 1) * 16;

    // ---- Q fragments: fp16, pre-scaled. a0=(qr,k2qc),a1=(qr+8,·),a2=(qr,k+8),a3=(qr+8,·)
    const float* qbase = g_Q + ((size_t)h * NTOK + q0 + wid * 16) * HD;
    uint32_t qf[4][4];
    #pragma unroll
    for (int kk = 0; kk < 4; kk++) {
        int k0 = kk * 16 + 2 * qc;
        qf[kk][0] = f2h2(qbase[(size_t)qr       * HD + k0]     * SCALE,
                         qbase[(size_t)qr       * HD + k0 + 1] * SCALE);
        qf[kk][1] = f2h2(qbase[(size_t)(qr + 8) * HD + k0]     * SCALE,
                         qbase[(size_t)(qr + 8) * HD + k0 + 1] * SCALE);
        qf[kk][2] = f2h2(qbase[(size_t)qr       * HD + k0 + 8] * SCALE,
                         qbase[(size_t)qr       * HD + k0 + 9] * SCALE);
        qf[kk][3] = f2h2(qbase[(size_t)(qr + 8) * HD + k0 + 8] * SCALE,
                         qbase[(size_t)(qr + 8) * HD + k0 + 9] * SCALE);
    }

    float m0 = -1e30f, m1 = -1e30f, l0 = 0.f, l1 = 0.f;
    float o[8][4];
    #pragma unroll
    for (int nb = 0; nb < 8; nb++)
        #pragma unroll
        for (int r = 0; r < 4; r++) o[nb][r] = 0.f;

    const float* kb = g_K + (size_t)h * NTOK * HD;
    const float* vb = g_V + (size_t)h * NTOK * HD;

    #pragma unroll 1
    for (int t = 0; t < NTOK; t += 64) {
        // ---- K/V tile load -> half2 smem ----
        #pragma unroll
        for (int i = 0; i < 4; i++) {
            int v = tid + i * 256;
            int r = v >> 4;
            int c = (v & 15) * 4;      // element col
            float4 fk = *(const float4*)&kb[(size_t)(t + r) * HD + c];
            float4 fv = *(const float4*)&vb[(size_t)(t + r) * HD + c];
            uint2 wk, wv;
            wk.x = f2h2(fk.x, fk.y);  wk.y = f2h2(fk.z, fk.w);
            wv.x = f2h2(fv.x, fv.y);  wv.y = f2h2(fv.z, fv.w);
            *(uint2*)&Ks2[r * H2ST + (v & 15) * 2] = wk;
            *(uint2*)&Vs2[r * H2ST + (v & 15) * 2] = wv;
        }
        __syncthreads();

        // ---- S = Q K^T : per nb-pair, 4 ldsm.x4 (kk) + 8 MMAs ----
        float sfr[8][4];
        #pragma unroll
        for (int nb = 0; nb < 8; nb++)
            #pragma unroll
            for (int r = 0; r < 4; r++) sfr[nb][r] = 0.f;

        #pragma unroll
        for (int nbp = 0; nbp < 4; nbp++) {
            uint32_t fB[4][4];
            #pragma unroll
            for (int kk = 0; kk < 4; kk++)
                ldsm_x4(fB[kk][0], fB[kk][1], fB[kk][2], fB[kk][3],
                        ks_lane + nbp * 16 * H2STB + kk * 32);
            int nb = nbp * 2;
            #pragma unroll
            for (int kk = 0; kk < 4; kk++) {
                mma_f16(sfr[nb][0], sfr[nb][1], sfr[nb][2], sfr[nb][3],
                        qf[kk][0], qf[kk][1], qf[kk][2], qf[kk][3],
                        fB[kk][0], fB[kk][1]);
                mma_f16(sfr[nb+1][0], sfr[nb+1][1], sfr[nb+1][2], sfr[nb+1][3],
                        qf[kk][0], qf[kk][1], qf[kk][2], qf[kk][3],
                        fB[kk][2], fB[kk][3]);
            }
        }

        // ---- online softmax (fp32) ----
        float mt0 = m0, mt1 = m1;
        #pragma unroll
        for (int nb = 0; nb < 8; nb++) {
            mt0 = fmaxf(mt0, fmaxf(sfr[nb][0], sfr[nb][1]));
            mt1 = fmaxf(mt1, fmaxf(sfr[nb][2], sfr[nb][3]));
        }
        mt0 = fmaxf(mt0, __shfl_xor_sync(0xffffffff, mt0, 1));
        mt0 = fmaxf(mt0, __shfl_xor_sync(0xffffffff, mt0, 2));
        mt1 = fmaxf(mt1, __shfl_xor_sync(0xffffffff, mt1, 1));
        mt1 = fmaxf(mt1, __shfl_xor_sync(0xffffffff, mt1, 2));

        float c0 = __expf(m0 - mt0);
        float c1 = __expf(m1 - mt1);
        m0 = mt0; m1 = mt1;
        l0 *= c0; l1 *= c1;
        #pragma unroll
        for (int nb = 0; nb < 8; nb++) {
            o[nb][0] *= c0; o[nb][1] *= c0;
            o[nb][2] *= c1; o[nb][3] *= c1;
        }

        // ---- P = exp(S - m) -> half2 Ps (C-frag cols 2qc,2qc+1 adjacent) ----
        {
            int r0 = (wid * 16 + qr) * H2ST;
            int r1 = r0 + 8 * H2ST;
            #pragma unroll
            for (int nb = 0; nb < 8; nb++) {
                float p0 = __expf(sfr[nb][0] - m0);
                float p1 = __expf(sfr[nb][1] - m0);
                float p2 = __expf(sfr[nb][2] - m1);
                float p3 = __expf(sfr[nb][3] - m1);
                l0 += p0 + p1;
                l1 += p2 + p3;
                Ps2[r0 + nb * 4 + qc] = f2h2(p0, p1);
                Ps2[r1 + nb * 4 + qc] = f2h2(p2, p3);
            }
        }
        __syncwarp();

        // ---- O += P V : P A-frags once (4 ldsm.x4), V via ldsm.x4.trans ----
        {
            uint32_t pf[4][4];   // [kk][m0,m1,m2,m3] -> a0=r0, a1=r2, a2=r1, a3=r3
            #pragma unroll
            for (int kk = 0; kk < 4; kk++)
                ldsm_x4(pf[kk][0], pf[kk][1], pf[kk][2], pf[kk][3],
                        ps_lane + kk * 32);
            #pragma unroll
            for (int nbp = 0; nbp < 4; nbp++) {
                uint32_t vf[4][4];
                #pragma unroll
                for (int kk = 0; kk < 4; kk++)
                    ldsm_x4t(vf[kk][0], vf[kk][1], vf[kk][2], vf[kk][3],
                             vs_lane + kk * 16 * H2STB + nbp * 32);
                int nb = nbp * 2;
                #pragma unroll
                for (int kk = 0; kk < 4; kk++) {
                    mma_f16(o[nb][0], o[nb][1], o[nb][2], o[nb][3],
                            pf[kk][0], pf[kk][2], pf[kk][1], pf[kk][3],
                            vf[kk][0], vf[kk][1]);
                    mma_f16(o[nb+1][0], o[nb+1][1], o[nb+1][2], o[nb+1][3],
                            pf[kk][0], pf[kk][2], pf[kk][1], pf[kk][3],
                            vf[kk][2], vf[kk][3]);
                }
            }
        }
        __syncthreads();
    }

    l0 += __shfl_xor_sync(0xffffffff, l0, 1);
    l0 += __shfl_xor_sync(0xffffffff, l0, 2);
    l1 += __shfl_xor_sync(0xffffffff, l1, 1);
    l1 += __shfl_xor_sync(0xffffffff, l1, 2);
    float inv0 = 1.f / l0;
    float inv1 = 1.f / l1;

    int row0 = q0 + wid * 16 + qr;
    #pragma unroll
    for (int nb = 0; nb < 8; nb++) {
        int col = h * HD + nb * 8 + 2 * qc;
        float2 w0, w1;
        w0.x = o[nb][0] * inv0; w0.y = o[nb][1] * inv0;
        w1.x = o[nb][2] * inv1; w1.y = o[nb][3] * inv1;
        *(float2*)&g_attn[(size_t)row0 * DIM + col] = w0;
        *(float2*)&g_attn[(size_t)(row0 + 8) * DIM + col] = w1;
    }
}

#define ATT_SMEM ((128 * H2ST + 128 * H2ST) * 4)   // K+V (64+64 rows) + P (128 rows)

// ---------------- launch ----------------
extern "C" void kernel_launch(void* const* d_in, const int* in_sizes, int n_in,
                              void* d_out, int out_size)
{
    const float* x      = (const float*)d_in[0];
    const float* cosb   = (const float*)d_in[1];
    const float* sinb   = (const float*)d_in[2];
    const float* w_qkv  = (const float*)d_in[3];
    const float* b_qkv  = (const float*)d_in[4];
    const float* w_proj = (const float*)d_in[5];
    const float* b_proj = (const float*)d_in[6];
    float* out = (float*)d_out;

    float *p_qkv, *p_attn;
    cudaGetSymbolAddress((void**)&p_qkv, g_qkv);
    cudaGetSymbolAddress((void**)&p_attn, g_attn);

    cudaFuncSetAttribute(attn_mma_kernel,
                         cudaFuncAttributeMaxDynamicSharedMemorySize, ATT_SMEM);

    // 1) QKV GEMM (tf32)
    {
        dim3 grid(QKV_N / GBN, NTOK / GBM);
        gemm_tf32_kernel<<<grid, 256>>>(x, w_qkv, b_qkv, p_qkv, NTOK, QKV_N, DIM);
    }
    // 2) RoPE + split
    {
        int total = NTOK * NHEADS * 32;
        rope_split_kernel<<<(total + 255) / 256, 256>>>(cosb, sinb);
    }
    // 3) attention (fp16 MMA, fp32 softmax)
    {
        dim3 grid(NTOK / ATT_BQ, NHEADS);
        attn_mma_kernel<<<grid, 256, ATT_SMEM>>>();
    }
    // 4) proj GEMM (tf32)
    {
        dim3 grid(DIM / GBN, NTOK / GBM);
        gemm_tf32_kernel<<<grid, 256>>>(p_attn, w_proj, b_proj, out, NTOK, DIM, DIM);
    }
}